// round 15
// baseline (speedup 1.0000x reference)
#include <cuda_runtime.h>
#include <cuda_bf16.h>
#include <math.h>

#define T_  8
#define N_  20000
#define E_  320000
#define DIN 64
#define H_  128
#define EPSB 1e-5f

#define SCAN_N (T_*N_)
#define TE (T_*E_)
#define NB 8
#define CAP 64          // bucket capacity per node (P(deg>64) ~ 1e-20)

// ---------- scratch ----------
__device__ float         g_dinv [SCAN_N];
__device__ float         g_w2   [SCAN_N];
__device__ int           g_cursor[SCAN_N];
__device__ int           g_bkt  [(size_t)SCAN_N*CAP];
__device__ __nv_bfloat16 g_yb   [(size_t)SCAN_N*64];
__device__ __nv_bfloat16 g_agg  [(size_t)SCAN_N*64];
__device__ float         g_S    [T_*H_];
__device__ float4        g_WT4  [4][32*512];
__device__ float         g_bsumL[2][512];
__device__ float         g_gatesG[2][512];      // cross-CTA gate exchange
__device__ unsigned      g_tick = 0;            // monotonic ticket barrier

// ---------- helpers ----------
__device__ __forceinline__ unsigned long long pk2(float a, float b) {
    unsigned long long r;
    asm("mov.b64 %0, {%1, %2};" : "=l"(r) : "f"(a), "f"(b));
    return r;
}
__device__ __forceinline__ unsigned long long ffma2(unsigned long long a,
                                                    unsigned long long b,
                                                    unsigned long long c) {
    unsigned long long d;
    asm("fma.rn.f32x2 %0, %1, %2, %3;" : "=l"(d) : "l"(a), "l"(b), "l"(c));
    return d;
}
__device__ __forceinline__ float2 upk2(unsigned long long v) {
    float2 f;
    asm("mov.b64 {%0, %1}, %2;" : "=f"(f.x), "=f"(f.y) : "l"(v));
    return f;
}
__device__ __forceinline__ __nv_bfloat162 asb2(unsigned u) {
    __nv_bfloat162 r; *reinterpret_cast<unsigned*>(&r) = u; return r;
}
__device__ __forceinline__ unsigned asu(__nv_bfloat162 h) {
    return *reinterpret_cast<unsigned*>(&h);
}
__device__ __forceinline__ unsigned scaleb2(unsigned a, float d) {
    float2 f = __bfloat1622float2(asb2(a));
    return asu(__floats2bfloat162_rn(f.x*d, f.y*d));
}
__device__ __forceinline__ float sigf(float x) { return 1.f / (1.f + expf(-x)); }

// ---------- K1: single-pass bucket fill + LSTM weight prep ----------
__global__ void __launch_bounds__(256) k_fillb(const int* __restrict__ ei,
                        const float* __restrict__ Wih0, const float* __restrict__ Whh0,
                        const float* __restrict__ Wih1, const float* __restrict__ Whh1,
                        const float* __restrict__ bih0, const float* __restrict__ bhh0,
                        const float* __restrict__ bih1, const float* __restrict__ bhh1) {
    int tid = threadIdx.x;
    if (blockIdx.x < 256) {
        int p = blockIdx.x * 256 + tid;              // 0..65535
        if (p < 1024) {
            int L = p >> 9, r = p & 511;
            g_bsumL[L][r] = L ? (bih1[r] + bhh1[r]) : (bih0[r] + bhh0[r]);
        }
        int m = p >> 14, rem = p & 16383;
        int k4 = rem >> 9, r = rem & 511;
        const float* W = (m == 0) ? Wih0 : (m == 1) ? Whh0 : (m == 2) ? Wih1 : Whh1;
        g_WT4[m][k4*512 + r] = ((const float4*)W)[r*32 + k4];
    }
    int i = blockIdx.x * 256 + tid;
    if (i >= TE/4) return;
    int t = i / (E_/4), e4 = i - t*(E_/4);
    int4 s4 = ((const int4*)(ei + t*2*E_))[e4];
    int4 d4 = ((const int4*)(ei + t*2*E_ + E_))[e4];
    int base = t*N_;
#pragma unroll
    for (int u = 0; u < 4; u++) {
        int src = (u == 0) ? s4.x : (u == 1) ? s4.y : (u == 2) ? s4.z : s4.w;
        int dst = (u == 0) ? d4.x : (u == 1) ? d4.y : (u == 2) ? d4.z : d4.w;
        int nd = base + dst;
        int pos = atomicAdd(&g_cursor[nd], 1);
        if (pos < CAP) g_bkt[(size_t)nd*CAP + pos] = src;
    }
}

// ---------- K2: dinv/w2-self + bf16 y-scale + zero S ----------
__global__ void __launch_bounds__(512) k_prep(const float* __restrict__ x) {
    int tid = threadIdx.x;
    if (blockIdx.x == 0 && tid < T_*H_) {
        g_S[tid] = 0.f;
        g_S[tid + 512] = 0.f;
    }
    int i = blockIdx.x*512 + tid;
    if (i >= SCAN_N*16) return;
    int node = i >> 4;
    float d = rsqrtf(1.0f + (float)g_cursor[node]);
    if ((i & 15) == 0) {
        g_dinv[node] = d;
        g_w2[node]   = d * d;
    }
    float4 vv = ((const float4*)x)[i];
    __nv_bfloat162 p0 = __floats2bfloat162_rn(d*vv.x, d*vv.y);
    __nv_bfloat162 p1 = __floats2bfloat162_rn(d*vv.z, d*vv.w);
    uint2 st; st.x = asu(p0); st.y = asu(p1);
    ((uint2*)(g_yb + (size_t)node*64))[i & 15] = st;
}

// ---------- K3: gather (8 lanes/node) + w2 edge REDG ----------
__global__ void __launch_bounds__(256) k_gather() {
    int tid = threadIdx.x;
    int t = blockIdx.y;
    int l = tid & 7;
    const uint4* yb4 = (const uint4*)g_yb + (size_t)t*N_*8;
    uint4*       ag4 = (uint4*)g_agg      + (size_t)t*N_*8;

    for (int i = blockIdx.x*32 + (tid >> 3); i < N_; i += gridDim.x*32) {
        int node = t*N_ + i;
        int cnt = min(g_cursor[node], CAP);
        const int* bp = g_bkt + (size_t)node*CAP;
        float dd = g_dinv[node];

        // w2 edge terms: lanes partition edges; REDG to src
        for (int j = l; j < cnt; j += 8) {
            int s = bp[j];
            float ds_ = g_dinv[t*N_ + s];
            atomicAdd(&g_w2[t*N_ + s], ds_ * dd);
        }

        // feature aggregation (lane = 16B chunk)
        uint4 sv = yb4[(size_t)i*8 + l];
        __nv_bfloat162 A0 = asb2(sv.x), A1 = asb2(sv.y),
                       A2 = asb2(sv.z), A3 = asb2(sv.w);
#pragma unroll 4
        for (int j = 0; j < cnt; j++) {
            int s = bp[j];
            uint4 vv = yb4[(size_t)s*8 + l];
            A0 = __hadd2(A0, asb2(vv.x));
            A1 = __hadd2(A1, asb2(vv.y));
            A2 = __hadd2(A2, asb2(vv.z));
            A3 = __hadd2(A3, asb2(vv.w));
        }
        uint4 st;
        st.x = scaleb2(asu(A0), dd);
        st.y = scaleb2(asu(A1), dd);
        st.z = scaleb2(asu(A2), dd);
        st.w = scaleb2(asu(A3), dd);
        ag4[(size_t)i*8 + l] = st;
    }
}

// ---------- K4: streamed NB=8 reg-tiled matmul + BN1 + ReLU + weighted reduce ----------
__global__ void __launch_bounds__(256) k_mm(const float* __restrict__ W1,
                                            const float* __restrict__ b1,
                                            const float* __restrict__ g1,
                                            const float* __restrict__ be1,
                                            const float* __restrict__ m1,
                                            const float* __restrict__ v1) {
    __shared__ float2 W1p[2][DIN*32];
    __shared__ float  sAcc[8][4][32];
    __shared__ float  sAgg[8][NB][DIN];
    int tid = threadIdx.x, lane = tid & 31, w = tid >> 5;
    int t = blockIdx.y;

    for (int ii = tid; ii < 2*DIN*32; ii += 256) {
        int p = ii >> 11, rem = ii & 2047;
        int k = rem >> 5, ll = rem & 31;
        W1p[p][k*32 + ll] = make_float2(W1[k*H_ + p*64 + ll],
                                        W1[k*H_ + p*64 + ll + 32]);
    }
    float sc[4], sh[4];
#pragma unroll
    for (int q = 0; q < 4; q++) {
        int j = lane + 32*q;
        float s = g1[j] * rsqrtf(v1[j] + EPSB);
        sc[q] = s;
        sh[q] = (b1[j] - m1[j]) * s + be1[j];
    }
    __syncthreads();

    const unsigned long long* Wp0 = (const unsigned long long*)W1p[0];
    const unsigned long long* Wp1 = (const unsigned long long*)W1p[1];
    const uint4* ag4 = (const uint4*)g_agg + (size_t)t*N_*8;
    float acc[4] = {0.f, 0.f, 0.f, 0.f};

    int stride = gridDim.x * 8 * NB;
    for (int i0 = (blockIdx.x*8 + w)*NB; i0 < N_; i0 += stride) {
#pragma unroll
        for (int cc = 0; cc < 2; cc++) {
            int chunk = lane + cc*32;
            int u = chunk >> 3, c8 = chunk & 7;
            int iu = min(i0 + u, N_ - 1);
            uint4 v = ag4[(size_t)iu*8 + c8];
            float2 f0 = __bfloat1622float2(asb2(v.x));
            float2 f1 = __bfloat1622float2(asb2(v.y));
            float2 f2 = __bfloat1622float2(asb2(v.z));
            float2 f3 = __bfloat1622float2(asb2(v.w));
            *(float4*)&sAgg[w][u][c8*8]     = make_float4(f0.x, f0.y, f1.x, f1.y);
            *(float4*)&sAgg[w][u][c8*8 + 4] = make_float4(f2.x, f2.y, f3.x, f3.y);
        }
        __syncwarp();

        unsigned long long P0[NB], P1[NB];
#pragma unroll
        for (int u = 0; u < NB; u++) { P0[u] = 0ull; P1[u] = 0ull; }
#pragma unroll 4
        for (int c = 0; c < 16; c++) {
            int k = c*4;
            unsigned long long w00 = Wp0[(k+0)*32 + lane];
            unsigned long long w01 = Wp0[(k+1)*32 + lane];
            unsigned long long w02 = Wp0[(k+2)*32 + lane];
            unsigned long long w03 = Wp0[(k+3)*32 + lane];
            unsigned long long w10 = Wp1[(k+0)*32 + lane];
            unsigned long long w11 = Wp1[(k+1)*32 + lane];
            unsigned long long w12 = Wp1[(k+2)*32 + lane];
            unsigned long long w13 = Wp1[(k+3)*32 + lane];
#pragma unroll
            for (int u = 0; u < NB; u++) {
                float4 b = *(const float4*)&sAgg[w][u][c*4];
                unsigned long long c2;
                c2 = pk2(b.x, b.x); P0[u] = ffma2(c2, w00, P0[u]);
                                    P1[u] = ffma2(c2, w10, P1[u]);
                c2 = pk2(b.y, b.y); P0[u] = ffma2(c2, w01, P0[u]);
                                    P1[u] = ffma2(c2, w11, P1[u]);
                c2 = pk2(b.z, b.z); P0[u] = ffma2(c2, w02, P0[u]);
                                    P1[u] = ffma2(c2, w12, P1[u]);
                c2 = pk2(b.w, b.w); P0[u] = ffma2(c2, w03, P0[u]);
                                    P1[u] = ffma2(c2, w13, P1[u]);
            }
        }

#pragma unroll
        for (int u = 0; u < NB; u++) {
            int iu = i0 + u;
            float wi = (iu < N_) ? g_w2[t*N_ + iu] : 0.f;
            float2 y01 = upk2(P0[u]), y23 = upk2(P1[u]);
            acc[0] += wi * fmaxf(y01.x*sc[0] + sh[0], 0.f);
            acc[1] += wi * fmaxf(y01.y*sc[1] + sh[1], 0.f);
            acc[2] += wi * fmaxf(y23.x*sc[2] + sh[2], 0.f);
            acc[3] += wi * fmaxf(y23.y*sc[3] + sh[3], 0.f);
        }
        __syncwarp();
    }
#pragma unroll
    for (int q = 0; q < 4; q++) sAcc[w][q][lane] = acc[q];
    __syncthreads();
    if (tid < 128) {
        int q = tid >> 5, ll = tid & 31;
        float s = 0.f;
#pragma unroll
        for (int ww = 0; ww < 8; ww++) s += sAcc[ww][q][ll];
        atomicAdd(&g_S[t*H_ + q*32 + ll], s);
    }
}

// ---------- K5: 8-CTA finalize with gmem ticket barrier ----------
// CTA rank owns gate rows [rank*64, rank*64+64); weights slice = 128KB -> L1.
// Ticket barrier: monotonic counter; a step's 8 arrivals occupy one aligned
// 8-block of tickets (steps are separated by the barrier itself; replays are
// stream-serialized), so spin target = ((ticket>>3)+1)<<3. No reset needed.
__global__ void __launch_bounds__(64)
k_final(const float* __restrict__ W2, const float* __restrict__ b2,
        const float* __restrict__ g2, const float* __restrict__ be2,
        const float* __restrict__ m2, const float* __restrict__ v2,
        const float* __restrict__ Wc, const float* __restrict__ bc,
        float* __restrict__ out) {
    __shared__ float Ssm[T_*H_];
    __shared__ float emb[T_][H_];
    __shared__ float hs[2][H_], cs[2][H_];
    int tid = threadIdx.x;
    int rank = blockIdx.x;

    for (int i = tid; i < T_*H_; i += 64) Ssm[i] = g_S[i] * (1.0f / N_);
    hs[0][tid] = 0.f; hs[0][tid+64] = 0.f; hs[1][tid] = 0.f; hs[1][tid+64] = 0.f;
    cs[0][tid] = 0.f; cs[0][tid+64] = 0.f; cs[1][tid] = 0.f; cs[1][tid+64] = 0.f;
    __syncthreads();

    // emb: redundant per CTA (1024 dot-128 products over 64 threads; trivial)
    for (int item = tid; item < T_*H_; item += 64) {
        int t = item >> 7, j = item & 127;
        float s2  = g2[j] * rsqrtf(v2[j] + EPSB);
        float sh2 = be2[j] - m2[j]*s2;
        float acc = b2[j];
#pragma unroll 8
        for (int k = 0; k < H_; k++) acc += Ssm[t*H_ + k] * W2[k*H_ + j];
        emb[t][j] = acc*s2 + sh2;
    }
    __syncthreads();

    int r = rank*64 + tid;                    // global gate row
    const float4* WI[2] = {(const float4*)g_WT4[0], (const float4*)g_WT4[2]};
    const float4* WH[2] = {(const float4*)g_WT4[1], (const float4*)g_WT4[3]};

    for (int ls = 0; ls < 2*T_; ls++) {
        int t = ls >> 1, layer = ls & 1;
        const float4* in4 = (const float4*)(layer ? hs[0] : emb[t]);
        const float4* hh4 = (const float4*)hs[layer];
        const float4* Wi  = WI[layer];
        const float4* Wh  = WH[layer];
        float acc = g_bsumL[layer][r];
#pragma unroll 8
        for (int k4 = 0; k4 < 32; k4++) {
            float4 wx = Wi[k4*512 + r];
            float4 wh = Wh[k4*512 + r];
            float4 xi = in4[k4];
            float4 hi = hh4[k4];
            acc += wx.x*xi.x + wx.y*xi.y + wx.z*xi.z + wx.w*xi.w;
            acc += wh.x*hi.x + wh.y*hi.y + wh.z*hi.z + wh.w*hi.w;
        }
        int buf = ls & 1;
        g_gatesG[buf][r] = acc;               // publish my gate row
        __threadfence();
        __syncthreads();
        if (tid == 0) {
            unsigned tk = atomicAdd(&g_tick, 1u);
            unsigned target = ((tk >> 3) + 1u) << 3;
            while (*((volatile unsigned*)&g_tick) < target) {}
            __threadfence();
        }
        __syncthreads();
        // redundant local h/c update from ALL gates (L1-bypassing loads)
        for (int j = tid; j < H_; j += 64) {
            float ig = sigf(__ldcg(&g_gatesG[buf][j]));
            float fg = sigf(__ldcg(&g_gatesG[buf][H_ + j]));
            float gg = tanhf(__ldcg(&g_gatesG[buf][2*H_ + j]));
            float og = sigf(__ldcg(&g_gatesG[buf][3*H_ + j]));
            float cn = fg*cs[layer][j] + ig*gg;
            cs[layer][j] = cn;
            hs[layer][j] = og * tanhf(cn);
        }
        __syncthreads();
    }

    if (rank == 0) {
        if (tid < 2) {
            float acc = bc[tid];
#pragma unroll 8
            for (int k = 0; k < H_; k++) acc += Wc[tid*H_ + k] * hs[1][k];
            out[tid] = acc;
        }
        out[2 + tid]      = hs[1][tid];
        out[2 + tid + 64] = hs[1][tid + 64];
    }
}

// ---------- launch ----------
extern "C" void kernel_launch(void* const* d_in, const int* in_sizes, int n_in,
                              void* d_out, int out_size) {
    const float* x    = (const float*)d_in[0];
    const int*   ei   = (const int*)  d_in[1];
    const float* W1   = (const float*)d_in[2];
    const float* b1   = (const float*)d_in[3];
    const float* g1   = (const float*)d_in[4];
    const float* be1  = (const float*)d_in[5];
    const float* m1   = (const float*)d_in[6];
    const float* v1   = (const float*)d_in[7];
    const float* W2   = (const float*)d_in[8];
    const float* b2   = (const float*)d_in[9];
    const float* g2   = (const float*)d_in[10];
    const float* be2  = (const float*)d_in[11];
    const float* m2   = (const float*)d_in[12];
    const float* v2   = (const float*)d_in[13];
    const float* Wih0 = (const float*)d_in[14];
    const float* Whh0 = (const float*)d_in[15];
    const float* bih0 = (const float*)d_in[16];
    const float* bhh0 = (const float*)d_in[17];
    const float* Wih1 = (const float*)d_in[18];
    const float* Whh1 = (const float*)d_in[19];
    const float* bih1 = (const float*)d_in[20];
    const float* bhh1 = (const float*)d_in[21];
    const float* Wc   = (const float*)d_in[22];
    const float* bc   = (const float*)d_in[23];

    void* curp = nullptr;
    cudaGetSymbolAddress(&curp, g_cursor);
    cudaMemsetAsync(curp, 0, SCAN_N * sizeof(int));

    k_fillb <<<(TE/4 + 255)/256, 256>>>(ei, Wih0, Whh0, Wih1, Whh1,
                                        bih0, bhh0, bih1, bhh1);
    k_prep  <<<(SCAN_N*16 + 511)/512, 512>>>(x);
    k_gather<<<dim3(148, T_), 256>>>();
    k_mm    <<<dim3(74, T_), 256>>>(W1, b1, g1, be1, m1, v1);
    k_final <<<8, 64>>>(W2, b2, g2, be2, m2, v2, Wc, bc, (float*)d_out);
}

// round 16
// speedup vs baseline: 1.4275x; 1.4275x over previous
#include <cuda_runtime.h>
#include <cuda_bf16.h>
#include <math.h>

#define T_  8
#define N_  20000
#define E_  320000
#define DIN 64
#define H_  128
#define EPSB 1e-5f

#define SCAN_N (T_*N_)
#define TE (T_*E_)
#define NB 8
#define CAP 64          // bucket capacity per node (P(deg>64) ~ 1e-20)

// ---------- scratch ----------
__device__ float         g_dinv [SCAN_N];
__device__ float         g_w2   [SCAN_N];
__device__ int           g_cursor[SCAN_N];
__device__ int           g_bkt  [(size_t)SCAN_N*CAP];
__device__ __nv_bfloat16 g_yb   [(size_t)SCAN_N*64];
__device__ __nv_bfloat16 g_agg  [(size_t)SCAN_N*64];
__device__ float         g_S    [T_*H_];
__device__ float4        g_WT4  [4][32*512];
__device__ float         g_bsumL[2][512];
__device__ float         g_h0buf[T_][H_];       // layer0 -> layer1 handoff
__device__ unsigned      g_flag [T_];           // zero-init; consume-then-reset

// ---------- helpers ----------
__device__ __forceinline__ unsigned long long pk2(float a, float b) {
    unsigned long long r;
    asm("mov.b64 %0, {%1, %2};" : "=l"(r) : "f"(a), "f"(b));
    return r;
}
__device__ __forceinline__ unsigned long long ffma2(unsigned long long a,
                                                    unsigned long long b,
                                                    unsigned long long c) {
    unsigned long long d;
    asm("fma.rn.f32x2 %0, %1, %2, %3;" : "=l"(d) : "l"(a), "l"(b), "l"(c));
    return d;
}
__device__ __forceinline__ float2 upk2(unsigned long long v) {
    float2 f;
    asm("mov.b64 {%0, %1}, %2;" : "=f"(f.x), "=f"(f.y) : "l"(v));
    return f;
}
__device__ __forceinline__ __nv_bfloat162 asb2(unsigned u) {
    __nv_bfloat162 r; *reinterpret_cast<unsigned*>(&r) = u; return r;
}
__device__ __forceinline__ unsigned asu(__nv_bfloat162 h) {
    return *reinterpret_cast<unsigned*>(&h);
}
__device__ __forceinline__ unsigned scaleb2(unsigned a, float d) {
    float2 f = __bfloat1622float2(asb2(a));
    return asu(__floats2bfloat162_rn(f.x*d, f.y*d));
}
__device__ __forceinline__ float sigf(float x) { return 1.f / (1.f + expf(-x)); }

// ---------- K1: single-pass bucket fill + LSTM weight prep ----------
__global__ void __launch_bounds__(256) k_fillb(const int* __restrict__ ei,
                        const float* __restrict__ Wih0, const float* __restrict__ Whh0,
                        const float* __restrict__ Wih1, const float* __restrict__ Whh1,
                        const float* __restrict__ bih0, const float* __restrict__ bhh0,
                        const float* __restrict__ bih1, const float* __restrict__ bhh1) {
    int tid = threadIdx.x;
    if (blockIdx.x < 256) {
        int p = blockIdx.x * 256 + tid;              // 0..65535
        if (p < 1024) {
            int L = p >> 9, r = p & 511;
            g_bsumL[L][r] = L ? (bih1[r] + bhh1[r]) : (bih0[r] + bhh0[r]);
        }
        int m = p >> 14, rem = p & 16383;
        int k4 = rem >> 9, r = rem & 511;
        const float* W = (m == 0) ? Wih0 : (m == 1) ? Whh0 : (m == 2) ? Wih1 : Whh1;
        g_WT4[m][k4*512 + r] = ((const float4*)W)[r*32 + k4];
    }
    int i = blockIdx.x * 256 + tid;
    if (i >= TE/4) return;
    int t = i / (E_/4), e4 = i - t*(E_/4);
    int4 s4 = ((const int4*)(ei + t*2*E_))[e4];
    int4 d4 = ((const int4*)(ei + t*2*E_ + E_))[e4];
    int base = t*N_;
#pragma unroll
    for (int u = 0; u < 4; u++) {
        int src = (u == 0) ? s4.x : (u == 1) ? s4.y : (u == 2) ? s4.z : s4.w;
        int dst = (u == 0) ? d4.x : (u == 1) ? d4.y : (u == 2) ? d4.z : d4.w;
        int nd = base + dst;
        int pos = atomicAdd(&g_cursor[nd], 1);
        if (pos < CAP) g_bkt[(size_t)nd*CAP + pos] = src;
    }
}

// ---------- K2: dinv/w2-self + bf16 y-scale + zero S ----------
__global__ void __launch_bounds__(512) k_prep(const float* __restrict__ x) {
    int tid = threadIdx.x;
    if (blockIdx.x == 0 && tid < T_*H_) {
        g_S[tid] = 0.f;
        g_S[tid + 512] = 0.f;
    }
    int i = blockIdx.x*512 + tid;
    if (i >= SCAN_N*16) return;
    int node = i >> 4;
    float d = rsqrtf(1.0f + (float)g_cursor[node]);
    if ((i & 15) == 0) {
        g_dinv[node] = d;
        g_w2[node]   = d * d;
    }
    float4 vv = ((const float4*)x)[i];
    __nv_bfloat162 p0 = __floats2bfloat162_rn(d*vv.x, d*vv.y);
    __nv_bfloat162 p1 = __floats2bfloat162_rn(d*vv.z, d*vv.w);
    uint2 st; st.x = asu(p0); st.y = asu(p1);
    ((uint2*)(g_yb + (size_t)node*64))[i & 15] = st;
}

// ---------- K3: gather (8 lanes/node) + w2 edge REDG ----------
__global__ void __launch_bounds__(256) k_gather() {
    int tid = threadIdx.x;
    int t = blockIdx.y;
    int l = tid & 7;
    const uint4* yb4 = (const uint4*)g_yb + (size_t)t*N_*8;
    uint4*       ag4 = (uint4*)g_agg      + (size_t)t*N_*8;

    for (int i = blockIdx.x*32 + (tid >> 3); i < N_; i += gridDim.x*32) {
        int node = t*N_ + i;
        int cnt = min(g_cursor[node], CAP);
        const int* bp = g_bkt + (size_t)node*CAP;
        float dd = g_dinv[node];

        for (int j = l; j < cnt; j += 8) {
            int s = bp[j];
            float ds_ = g_dinv[t*N_ + s];
            atomicAdd(&g_w2[t*N_ + s], ds_ * dd);
        }

        uint4 sv = yb4[(size_t)i*8 + l];
        __nv_bfloat162 A0 = asb2(sv.x), A1 = asb2(sv.y),
                       A2 = asb2(sv.z), A3 = asb2(sv.w);
#pragma unroll 4
        for (int j = 0; j < cnt; j++) {
            int s = bp[j];
            uint4 vv = yb4[(size_t)s*8 + l];
            A0 = __hadd2(A0, asb2(vv.x));
            A1 = __hadd2(A1, asb2(vv.y));
            A2 = __hadd2(A2, asb2(vv.z));
            A3 = __hadd2(A3, asb2(vv.w));
        }
        uint4 st;
        st.x = scaleb2(asu(A0), dd);
        st.y = scaleb2(asu(A1), dd);
        st.z = scaleb2(asu(A2), dd);
        st.w = scaleb2(asu(A3), dd);
        ag4[(size_t)i*8 + l] = st;
    }
}

// ---------- K4: streamed NB=8 reg-tiled matmul + BN1 + ReLU + weighted reduce ----------
__global__ void __launch_bounds__(256) k_mm(const float* __restrict__ W1,
                                            const float* __restrict__ b1,
                                            const float* __restrict__ g1,
                                            const float* __restrict__ be1,
                                            const float* __restrict__ m1,
                                            const float* __restrict__ v1) {
    __shared__ float2 W1p[2][DIN*32];
    __shared__ float  sAcc[8][4][32];
    __shared__ float  sAgg[8][NB][DIN];
    int tid = threadIdx.x, lane = tid & 31, w = tid >> 5;
    int t = blockIdx.y;

    for (int ii = tid; ii < 2*DIN*32; ii += 256) {
        int p = ii >> 11, rem = ii & 2047;
        int k = rem >> 5, ll = rem & 31;
        W1p[p][k*32 + ll] = make_float2(W1[k*H_ + p*64 + ll],
                                        W1[k*H_ + p*64 + ll + 32]);
    }
    float sc[4], sh[4];
#pragma unroll
    for (int q = 0; q < 4; q++) {
        int j = lane + 32*q;
        float s = g1[j] * rsqrtf(v1[j] + EPSB);
        sc[q] = s;
        sh[q] = (b1[j] - m1[j]) * s + be1[j];
    }
    __syncthreads();

    const unsigned long long* Wp0 = (const unsigned long long*)W1p[0];
    const unsigned long long* Wp1 = (const unsigned long long*)W1p[1];
    const uint4* ag4 = (const uint4*)g_agg + (size_t)t*N_*8;
    float acc[4] = {0.f, 0.f, 0.f, 0.f};

    int stride = gridDim.x * 8 * NB;
    for (int i0 = (blockIdx.x*8 + w)*NB; i0 < N_; i0 += stride) {
#pragma unroll
        for (int cc = 0; cc < 2; cc++) {
            int chunk = lane + cc*32;
            int u = chunk >> 3, c8 = chunk & 7;
            int iu = min(i0 + u, N_ - 1);
            uint4 v = ag4[(size_t)iu*8 + c8];
            float2 f0 = __bfloat1622float2(asb2(v.x));
            float2 f1 = __bfloat1622float2(asb2(v.y));
            float2 f2 = __bfloat1622float2(asb2(v.z));
            float2 f3 = __bfloat1622float2(asb2(v.w));
            *(float4*)&sAgg[w][u][c8*8]     = make_float4(f0.x, f0.y, f1.x, f1.y);
            *(float4*)&sAgg[w][u][c8*8 + 4] = make_float4(f2.x, f2.y, f3.x, f3.y);
        }
        __syncwarp();

        unsigned long long P0[NB], P1[NB];
#pragma unroll
        for (int u = 0; u < NB; u++) { P0[u] = 0ull; P1[u] = 0ull; }
#pragma unroll 4
        for (int c = 0; c < 16; c++) {
            int k = c*4;
            unsigned long long w00 = Wp0[(k+0)*32 + lane];
            unsigned long long w01 = Wp0[(k+1)*32 + lane];
            unsigned long long w02 = Wp0[(k+2)*32 + lane];
            unsigned long long w03 = Wp0[(k+3)*32 + lane];
            unsigned long long w10 = Wp1[(k+0)*32 + lane];
            unsigned long long w11 = Wp1[(k+1)*32 + lane];
            unsigned long long w12 = Wp1[(k+2)*32 + lane];
            unsigned long long w13 = Wp1[(k+3)*32 + lane];
#pragma unroll
            for (int u = 0; u < NB; u++) {
                float4 b = *(const float4*)&sAgg[w][u][c*4];
                unsigned long long c2;
                c2 = pk2(b.x, b.x); P0[u] = ffma2(c2, w00, P0[u]);
                                    P1[u] = ffma2(c2, w10, P1[u]);
                c2 = pk2(b.y, b.y); P0[u] = ffma2(c2, w01, P0[u]);
                                    P1[u] = ffma2(c2, w11, P1[u]);
                c2 = pk2(b.z, b.z); P0[u] = ffma2(c2, w02, P0[u]);
                                    P1[u] = ffma2(c2, w12, P1[u]);
                c2 = pk2(b.w, b.w); P0[u] = ffma2(c2, w03, P0[u]);
                                    P1[u] = ffma2(c2, w13, P1[u]);
            }
        }

#pragma unroll
        for (int u = 0; u < NB; u++) {
            int iu = i0 + u;
            float wi = (iu < N_) ? g_w2[t*N_ + iu] : 0.f;
            float2 y01 = upk2(P0[u]), y23 = upk2(P1[u]);
            acc[0] += wi * fmaxf(y01.x*sc[0] + sh[0], 0.f);
            acc[1] += wi * fmaxf(y01.y*sc[1] + sh[1], 0.f);
            acc[2] += wi * fmaxf(y23.x*sc[2] + sh[2], 0.f);
            acc[3] += wi * fmaxf(y23.y*sc[3] + sh[3], 0.f);
        }
        __syncwarp();
    }
#pragma unroll
    for (int q = 0; q < 4; q++) sAcc[w][q][lane] = acc[q];
    __syncthreads();
    if (tid < 128) {
        int q = tid >> 5, ll = tid & 31;
        float s = 0.f;
#pragma unroll
        for (int ww = 0; ww < 8; ww++) s += sAcc[ww][q][ll];
        atomicAdd(&g_S[t*H_ + q*32 + ll], s);
    }
}

// ---------- K5: 2-CTA layer-pipelined finalize ----------
// CTA0 = layer 0 (produces h0[t]); CTA1 = layer 1 (consumes h0[t], emits out).
// Gates stay CTA-local; only 128 floats/step cross CTAs via store->bar->fence->
// release-flag, acquire-spin + consume-then-reset (replay-safe, stream-ordered).
__global__ void __launch_bounds__(512)
k_final(const float* __restrict__ W2, const float* __restrict__ b2,
        const float* __restrict__ g2, const float* __restrict__ be2,
        const float* __restrict__ m2, const float* __restrict__ v2,
        const float* __restrict__ Wc, const float* __restrict__ bc,
        float* __restrict__ out) {
    __shared__ float Ssm[T_*H_];
    __shared__ float emb[T_][H_];
    __shared__ float hs[H_], cs[H_];
    __shared__ float gates[512];
    int tid = threadIdx.x;
    int r = tid;

    if (blockIdx.x == 0) {
        // ================= CTA0: layer 0 =================
        for (int i = tid; i < T_*H_; i += 512) Ssm[i] = g_S[i] * (1.0f / N_);
        if (tid < H_) { hs[tid] = 0.f; cs[tid] = 0.f; }
        __syncthreads();

        for (int item = tid; item < T_*H_; item += 512) {
            int t = item >> 7, j = item & 127;
            float s2  = g2[j] * rsqrtf(v2[j] + EPSB);
            float sh2 = be2[j] - m2[j]*s2;
            float acc = b2[j];
#pragma unroll 8
            for (int k = 0; k < H_; k++) acc += Ssm[t*H_ + k] * W2[k*H_ + j];
            emb[t][j] = acc*s2 + sh2;
        }
        __syncthreads();

        const float4* Wi = (const float4*)g_WT4[0];
        const float4* Wh = (const float4*)g_WT4[1];
        for (int t = 0; t < T_; t++) {
            const float4* in4 = (const float4*)emb[t];
            const float4* hh4 = (const float4*)hs;
            float acc = g_bsumL[0][r];
#pragma unroll 8
            for (int k4 = 0; k4 < 32; k4++) {
                float4 wx = Wi[k4*512 + r];
                float4 wh = Wh[k4*512 + r];
                float4 xi = in4[k4];
                float4 hi = hh4[k4];
                acc += wx.x*xi.x + wx.y*xi.y + wx.z*xi.z + wx.w*xi.w;
                acc += wh.x*hi.x + wh.y*hi.y + wh.z*hi.z + wh.w*hi.w;
            }
            gates[r] = acc;
            __syncthreads();
            if (tid < H_) {
                int j = tid;
                float ig = sigf(gates[j]);
                float fg = sigf(gates[H_ + j]);
                float gg = tanhf(gates[2*H_ + j]);
                float og = sigf(gates[3*H_ + j]);
                float cn = fg*cs[j] + ig*gg;
                cs[j] = cn;
                float hv = og * tanhf(cn);
                hs[j] = hv;
                g_h0buf[t][j] = hv;              // publish
            }
            __syncthreads();                      // all h0 stores issued (cumulativity via bar)
            if (tid == 0) {
                __threadfence();
                asm volatile("st.release.gpu.global.u32 [%0], %1;"
                             :: "l"(&g_flag[t]), "r"(1u) : "memory");
            }
        }
    } else {
        // ================= CTA1: layer 1 =================
        __shared__ float h0loc[H_];
        if (tid < H_) { hs[tid] = 0.f; cs[tid] = 0.f; }
        __syncthreads();

        const float4* Wi = (const float4*)g_WT4[2];
        const float4* Wh = (const float4*)g_WT4[3];
        for (int t = 0; t < T_; t++) {
            if (tid == 0) {
                unsigned v;
                do {
                    asm volatile("ld.acquire.gpu.global.u32 %0, [%1];"
                                 : "=r"(v) : "l"(&g_flag[t]) : "memory");
                } while (v == 0);
            }
            __syncthreads();
            if (tid < H_) h0loc[tid] = __ldcg(&g_h0buf[t][tid]);
            __syncthreads();

            const float4* in4 = (const float4*)h0loc;
            const float4* hh4 = (const float4*)hs;
            float acc = g_bsumL[1][r];
#pragma unroll 8
            for (int k4 = 0; k4 < 32; k4++) {
                float4 wx = Wi[k4*512 + r];
                float4 wh = Wh[k4*512 + r];
                float4 xi = in4[k4];
                float4 hi = hh4[k4];
                acc += wx.x*xi.x + wx.y*xi.y + wx.z*xi.z + wx.w*xi.w;
                acc += wh.x*hi.x + wh.y*hi.y + wh.z*hi.z + wh.w*hi.w;
            }
            gates[r] = acc;
            __syncthreads();
            if (tid < H_) {
                int j = tid;
                float ig = sigf(gates[j]);
                float fg = sigf(gates[H_ + j]);
                float gg = tanhf(gates[2*H_ + j]);
                float og = sigf(gates[3*H_ + j]);
                float cn = fg*cs[j] + ig*gg;
                cs[j] = cn;
                hs[j] = og * tanhf(cn);
            }
            if (tid == 0) g_flag[t] = 0;          // consume-then-reset (replay-safe)
            __syncthreads();
        }

        if (tid < 2) {
            float acc = bc[tid];
#pragma unroll 8
            for (int k = 0; k < H_; k++) acc += Wc[tid*H_ + k] * hs[k];
            out[tid] = acc;
        }
        if (tid < H_) out[2 + tid] = hs[tid];
    }
}

// ---------- launch ----------
extern "C" void kernel_launch(void* const* d_in, const int* in_sizes, int n_in,
                              void* d_out, int out_size) {
    const float* x    = (const float*)d_in[0];
    const int*   ei   = (const int*)  d_in[1];
    const float* W1   = (const float*)d_in[2];
    const float* b1   = (const float*)d_in[3];
    const float* g1   = (const float*)d_in[4];
    const float* be1  = (const float*)d_in[5];
    const float* m1   = (const float*)d_in[6];
    const float* v1   = (const float*)d_in[7];
    const float* W2   = (const float*)d_in[8];
    const float* b2   = (const float*)d_in[9];
    const float* g2   = (const float*)d_in[10];
    const float* be2  = (const float*)d_in[11];
    const float* m2   = (const float*)d_in[12];
    const float* v2   = (const float*)d_in[13];
    const float* Wih0 = (const float*)d_in[14];
    const float* Whh0 = (const float*)d_in[15];
    const float* bih0 = (const float*)d_in[16];
    const float* bhh0 = (const float*)d_in[17];
    const float* Wih1 = (const float*)d_in[18];
    const float* Whh1 = (const float*)d_in[19];
    const float* bih1 = (const float*)d_in[20];
    const float* bhh1 = (const float*)d_in[21];
    const float* Wc   = (const float*)d_in[22];
    const float* bc   = (const float*)d_in[23];

    void* curp = nullptr;
    cudaGetSymbolAddress(&curp, g_cursor);
    cudaMemsetAsync(curp, 0, SCAN_N * sizeof(int));

    k_fillb <<<(TE/4 + 255)/256, 256>>>(ei, Wih0, Whh0, Wih1, Whh1,
                                        bih0, bhh0, bih1, bhh1);
    k_prep  <<<(SCAN_N*16 + 511)/512, 512>>>(x);
    k_gather<<<dim3(148, T_), 256>>>();
    k_mm    <<<dim3(74, T_), 256>>>(W1, b1, g1, be1, m1, v1);
    k_final <<<2, 512>>>(W2, b2, g2, be2, m2, v2, Wc, bc, (float*)d_out);
}

// round 17
// speedup vs baseline: 1.7580x; 1.2315x over previous
#include <cuda_runtime.h>
#include <cuda_bf16.h>
#include <math.h>

#define T_  8
#define N_  20000
#define E_  320000
#define DIN 64
#define H_  128
#define EPSB 1e-5f

#define SCAN_N (T_*N_)
#define TE (T_*E_)
#define CAP 64          // bucket capacity per node (P(deg>64) ~ 1e-20)

// ---------- scratch ----------
__device__ float         g_dinv [SCAN_N];
__device__ float         g_w2   [SCAN_N];
__device__ int           g_cursor[SCAN_N];
__device__ int           g_bkt  [(size_t)SCAN_N*CAP];
__device__ __nv_bfloat16 g_yb   [(size_t)SCAN_N*64];
__device__ __nv_bfloat16 g_agg  [(size_t)SCAN_N*64];
__device__ float         g_S    [T_*H_];
__device__ float4        g_WT4  [4][32*512];
__device__ float         g_bsumL[2][512];
__device__ float         g_h0buf[T_][H_];       // layer0 -> layer1 handoff
__device__ unsigned      g_flag [T_];           // zero-init; consume-then-reset

// ---------- helpers ----------
__device__ __forceinline__ __nv_bfloat162 asb2(unsigned u) {
    __nv_bfloat162 r; *reinterpret_cast<unsigned*>(&r) = u; return r;
}
__device__ __forceinline__ unsigned asu(__nv_bfloat162 h) {
    return *reinterpret_cast<unsigned*>(&h);
}
__device__ __forceinline__ unsigned scaleb2(unsigned a, float d) {
    float2 f = __bfloat1622float2(asb2(a));
    return asu(__floats2bfloat162_rn(f.x*d, f.y*d));
}
__device__ __forceinline__ unsigned smem_u32(const void* p) {
    unsigned a;
    asm("{ .reg .u64 t; cvta.to.shared.u64 t, %1; cvt.u32.u64 %0, t; }"
        : "=r"(a) : "l"(p));
    return a;
}
__device__ __forceinline__ float sigf(float x) { return 1.f / (1.f + expf(-x)); }

// ---------- K1: single-pass bucket fill + LSTM weight prep ----------
__global__ void __launch_bounds__(256) k_fillb(const int* __restrict__ ei,
                        const float* __restrict__ Wih0, const float* __restrict__ Whh0,
                        const float* __restrict__ Wih1, const float* __restrict__ Whh1,
                        const float* __restrict__ bih0, const float* __restrict__ bhh0,
                        const float* __restrict__ bih1, const float* __restrict__ bhh1) {
    int tid = threadIdx.x;
    if (blockIdx.x < 256) {
        int p = blockIdx.x * 256 + tid;              // 0..65535
        if (p < 1024) {
            int L = p >> 9, r = p & 511;
            g_bsumL[L][r] = L ? (bih1[r] + bhh1[r]) : (bih0[r] + bhh0[r]);
        }
        int m = p >> 14, rem = p & 16383;
        int k4 = rem >> 9, r = rem & 511;
        const float* W = (m == 0) ? Wih0 : (m == 1) ? Whh0 : (m == 2) ? Wih1 : Whh1;
        g_WT4[m][k4*512 + r] = ((const float4*)W)[r*32 + k4];
    }
    int i = blockIdx.x * 256 + tid;
    if (i >= TE/4) return;
    int t = i / (E_/4), e4 = i - t*(E_/4);
    int4 s4 = ((const int4*)(ei + t*2*E_))[e4];
    int4 d4 = ((const int4*)(ei + t*2*E_ + E_))[e4];
    int base = t*N_;
#pragma unroll
    for (int u = 0; u < 4; u++) {
        int src = (u == 0) ? s4.x : (u == 1) ? s4.y : (u == 2) ? s4.z : s4.w;
        int dst = (u == 0) ? d4.x : (u == 1) ? d4.y : (u == 2) ? d4.z : d4.w;
        int nd = base + dst;
        int pos = atomicAdd(&g_cursor[nd], 1);
        if (pos < CAP) g_bkt[(size_t)nd*CAP + pos] = src;
    }
}

// ---------- K2: dinv/w2-self + bf16 y-scale + zero S ----------
__global__ void __launch_bounds__(512) k_prep(const float* __restrict__ x) {
    int tid = threadIdx.x;
    if (blockIdx.x == 0 && tid < T_*H_) {
        g_S[tid] = 0.f;
        g_S[tid + 512] = 0.f;
    }
    int i = blockIdx.x*512 + tid;
    if (i >= SCAN_N*16) return;
    int node = i >> 4;
    float d = rsqrtf(1.0f + (float)g_cursor[node]);
    if ((i & 15) == 0) {
        g_dinv[node] = d;
        g_w2[node]   = d * d;
    }
    float4 vv = ((const float4*)x)[i];
    __nv_bfloat162 p0 = __floats2bfloat162_rn(d*vv.x, d*vv.y);
    __nv_bfloat162 p1 = __floats2bfloat162_rn(d*vv.z, d*vv.w);
    uint2 st; st.x = asu(p0); st.y = asu(p1);
    ((uint2*)(g_yb + (size_t)node*64))[i & 15] = st;
}

// ---------- K3: gather (8 lanes/node) + w2 edge REDG ----------
__global__ void __launch_bounds__(256) k_gather() {
    int tid = threadIdx.x;
    int t = blockIdx.y;
    int l = tid & 7;
    const uint4* yb4 = (const uint4*)g_yb + (size_t)t*N_*8;
    uint4*       ag4 = (uint4*)g_agg      + (size_t)t*N_*8;

    for (int i = blockIdx.x*32 + (tid >> 3); i < N_; i += gridDim.x*32) {
        int node = t*N_ + i;
        int cnt = min(g_cursor[node], CAP);
        const int* bp = g_bkt + (size_t)node*CAP;
        float dd = g_dinv[node];

        for (int j = l; j < cnt; j += 8) {
            int s = bp[j];
            float ds_ = g_dinv[t*N_ + s];
            atomicAdd(&g_w2[t*N_ + s], ds_ * dd);
        }

        uint4 sv = yb4[(size_t)i*8 + l];
        __nv_bfloat162 A0 = asb2(sv.x), A1 = asb2(sv.y),
                       A2 = asb2(sv.z), A3 = asb2(sv.w);
#pragma unroll 4
        for (int j = 0; j < cnt; j++) {
            int s = bp[j];
            uint4 vv = yb4[(size_t)s*8 + l];
            A0 = __hadd2(A0, asb2(vv.x));
            A1 = __hadd2(A1, asb2(vv.y));
            A2 = __hadd2(A2, asb2(vv.z));
            A3 = __hadd2(A3, asb2(vv.w));
        }
        uint4 st;
        st.x = scaleb2(asu(A0), dd);
        st.y = scaleb2(asu(A1), dd);
        st.z = scaleb2(asu(A2), dd);
        st.w = scaleb2(asu(A3), dd);
        ag4[(size_t)i*8 + l] = st;
    }
}

// ---------- K4: tensor-core matmul (m16n8k16 bf16) + BN1 + ReLU + weighted reduce ----------
// Per warp: chunks of 16 nodes. A frags straight from g_agg (LDG.32 per canonical
// layout); B = W1*sc as bf16 in smem, stride 272B (LDSM-conflict-free), loaded
// via ldmatrix.x2.trans. Epilogue: relu(d + sh)*w2 accumulated per-lane, reduced
// once at kernel end (3 xor-shfls -> smem -> gmem atomic).
#define BSTRIDE 272
__global__ void __launch_bounds__(256) k_mmtc(const float* __restrict__ W1,
                                              const float* __restrict__ b1,
                                              const float* __restrict__ g1,
                                              const float* __restrict__ be1,
                                              const float* __restrict__ m1,
                                              const float* __restrict__ v1) {
    __shared__ __align__(16) char W1s[64*BSTRIDE];
    __shared__ float shs[H_];
    __shared__ float sS[H_];
    int tid = threadIdx.x, lane = tid & 31, w = tid >> 5;
    int t = blockIdx.y;
    int g = lane >> 2, tg = lane & 3;

    if (tid < H_) {
        int j = tid;
        float s = g1[j] * rsqrtf(v1[j] + EPSB);
        shs[j] = (b1[j] - m1[j]) * s + be1[j];
        sS[j]  = 0.f;
    }
    // fill B' = bf16(W1 * sc), row-major [64][128], stride 272B
    for (int idx = tid; idx < DIN*H_; idx += 256) {
        int k = idx >> 7, j = idx & 127;
        float s = g1[j] * rsqrtf(v1[j] + EPSB);
        *(__nv_bfloat16*)(W1s + k*BSTRIDE + j*2) = __float2bfloat16(W1[k*H_ + j] * s);
    }
    __syncthreads();

    unsigned wbase = smem_u32(W1s);
    // ldmatrix row address for this lane (rows of B within a k-step)
    int brow = lane & 15;

    float colacc[32];
#pragma unroll
    for (int q = 0; q < 32; q++) colacc[q] = 0.f;

    int warpsPerT = gridDim.x * 8;
    int warpId = blockIdx.x * 8 + w;

    for (int c = warpId; c < N_/16; c += warpsPerT) {
        int i0 = c * 16;
        const char* rowg  = (const char*)(g_agg + (size_t)(t*N_ + i0 + g)*64);
        const char* rowg8 = rowg + 8*64*2;
        // A fragments for all 4 k-steps (16 regs), canonical m16n8k16 layout
        unsigned a0[4], a1[4], a2[4], a3[4];
#pragma unroll
        for (int ks = 0; ks < 4; ks++) {
            a0[ks] = *(const unsigned*)(rowg  + ks*32 + tg*4);
            a1[ks] = *(const unsigned*)(rowg8 + ks*32 + tg*4);
            a2[ks] = *(const unsigned*)(rowg  + ks*32 + 16 + tg*4);
            a3[ks] = *(const unsigned*)(rowg8 + ks*32 + 16 + tg*4);
        }
        float wig  = g_w2[t*N_ + i0 + g];
        float wig8 = g_w2[t*N_ + i0 + g + 8];

#pragma unroll
        for (int tile = 0; tile < 16; tile++) {
            float d0 = 0.f, d1 = 0.f, d2 = 0.f, d3 = 0.f;
#pragma unroll
            for (int ks = 0; ks < 4; ks++) {
                unsigned b0, b1r;
                unsigned baddr = wbase + (unsigned)((ks*16 + brow)*BSTRIDE + tile*16);
                asm volatile("ldmatrix.sync.aligned.m8n8.x2.trans.shared.b16 {%0,%1}, [%2];"
                             : "=r"(b0), "=r"(b1r) : "r"(baddr));
                asm volatile("mma.sync.aligned.m16n8k16.row.col.f32.bf16.bf16.f32 "
                             "{%0,%1,%2,%3}, {%4,%5,%6,%7}, {%8,%9}, {%0,%1,%2,%3};"
                             : "+f"(d0), "+f"(d1), "+f"(d2), "+f"(d3)
                             : "r"(a0[ks]), "r"(a1[ks]), "r"(a2[ks]), "r"(a3[ks]),
                               "r"(b0), "r"(b1r));
            }
            float sh0 = shs[tile*8 + tg*2];
            float sh1 = shs[tile*8 + tg*2 + 1];
            colacc[2*tile]     += wig*fmaxf(d0 + sh0, 0.f) + wig8*fmaxf(d2 + sh0, 0.f);
            colacc[2*tile + 1] += wig*fmaxf(d1 + sh1, 0.f) + wig8*fmaxf(d3 + sh1, 0.f);
        }
    }

    // reduce colacc across the 8 lanes sharing each column (lane bits 2..4 = g)
#pragma unroll
    for (int q = 0; q < 32; q++) {
        float v = colacc[q];
        v += __shfl_xor_sync(0xffffffffu, v, 4);
        v += __shfl_xor_sync(0xffffffffu, v, 8);
        v += __shfl_xor_sync(0xffffffffu, v, 16);
        if (g == 0) {
            int col = (q >> 1)*8 + tg*2 + (q & 1);
            atomicAdd(&sS[col], v);
        }
    }
    __syncthreads();
    if (tid < H_) atomicAdd(&g_S[t*H_ + tid], sS[tid]);
}

// ---------- K5: 2-CTA layer-pipelined finalize ----------
__global__ void __launch_bounds__(512)
k_final(const float* __restrict__ W2, const float* __restrict__ b2,
        const float* __restrict__ g2, const float* __restrict__ be2,
        const float* __restrict__ m2, const float* __restrict__ v2,
        const float* __restrict__ Wc, const float* __restrict__ bc,
        float* __restrict__ out) {
    __shared__ float Ssm[T_*H_];
    __shared__ float emb[T_][H_];
    __shared__ float hs[H_], cs[H_];
    __shared__ float gates[512];
    int tid = threadIdx.x;
    int r = tid;

    if (blockIdx.x == 0) {
        // ================= CTA0: layer 0 =================
        for (int i = tid; i < T_*H_; i += 512) Ssm[i] = g_S[i] * (1.0f / N_);
        if (tid < H_) { hs[tid] = 0.f; cs[tid] = 0.f; }
        __syncthreads();

        for (int item = tid; item < T_*H_; item += 512) {
            int t = item >> 7, j = item & 127;
            float s2  = g2[j] * rsqrtf(v2[j] + EPSB);
            float sh2 = be2[j] - m2[j]*s2;
            float acc = b2[j];
#pragma unroll 8
            for (int k = 0; k < H_; k++) acc += Ssm[t*H_ + k] * W2[k*H_ + j];
            emb[t][j] = acc*s2 + sh2;
        }
        __syncthreads();

        const float4* Wi = (const float4*)g_WT4[0];
        const float4* Wh = (const float4*)g_WT4[1];
        for (int t = 0; t < T_; t++) {
            const float4* in4 = (const float4*)emb[t];
            const float4* hh4 = (const float4*)hs;
            float acc = g_bsumL[0][r];
#pragma unroll 8
            for (int k4 = 0; k4 < 32; k4++) {
                float4 wx = Wi[k4*512 + r];
                float4 wh = Wh[k4*512 + r];
                float4 xi = in4[k4];
                float4 hi = hh4[k4];
                acc += wx.x*xi.x + wx.y*xi.y + wx.z*xi.z + wx.w*xi.w;
                acc += wh.x*hi.x + wh.y*hi.y + wh.z*hi.z + wh.w*hi.w;
            }
            gates[r] = acc;
            __syncthreads();
            if (tid < H_) {
                int j = tid;
                float ig = sigf(gates[j]);
                float fg = sigf(gates[H_ + j]);
                float gg = tanhf(gates[2*H_ + j]);
                float og = sigf(gates[3*H_ + j]);
                float cn = fg*cs[j] + ig*gg;
                cs[j] = cn;
                float hv = og * tanhf(cn);
                hs[j] = hv;
                g_h0buf[t][j] = hv;              // publish
            }
            __syncthreads();
            if (tid == 0) {
                __threadfence();
                asm volatile("st.release.gpu.global.u32 [%0], %1;"
                             :: "l"(&g_flag[t]), "r"(1u) : "memory");
            }
        }
    } else {
        // ================= CTA1: layer 1 =================
        __shared__ float h0loc[H_];
        if (tid < H_) { hs[tid] = 0.f; cs[tid] = 0.f; }
        __syncthreads();

        const float4* Wi = (const float4*)g_WT4[2];
        const float4* Wh = (const float4*)g_WT4[3];
        for (int t = 0; t < T_; t++) {
            if (tid == 0) {
                unsigned v;
                do {
                    asm volatile("ld.acquire.gpu.global.u32 %0, [%1];"
                                 : "=r"(v) : "l"(&g_flag[t]) : "memory");
                } while (v == 0);
            }
            __syncthreads();
            if (tid < H_) h0loc[tid] = __ldcg(&g_h0buf[t][tid]);
            __syncthreads();

            const float4* in4 = (const float4*)h0loc;
            const float4* hh4 = (const float4*)hs;
            float acc = g_bsumL[1][r];
#pragma unroll 8
            for (int k4 = 0; k4 < 32; k4++) {
                float4 wx = Wi[k4*512 + r];
                float4 wh = Wh[k4*512 + r];
                float4 xi = in4[k4];
                float4 hi = hh4[k4];
                acc += wx.x*xi.x + wx.y*xi.y + wx.z*xi.z + wx.w*xi.w;
                acc += wh.x*hi.x + wh.y*hi.y + wh.z*hi.z + wh.w*hi.w;
            }
            gates[r] = acc;
            __syncthreads();
            if (tid < H_) {
                int j = tid;
                float ig = sigf(gates[j]);
                float fg = sigf(gates[H_ + j]);
                float gg = tanhf(gates[2*H_ + j]);
                float og = sigf(gates[3*H_ + j]);
                float cn = fg*cs[j] + ig*gg;
                cs[j] = cn;
                hs[j] = og * tanhf(cn);
            }
            if (tid == 0) g_flag[t] = 0;          // consume-then-reset (replay-safe)
            __syncthreads();
        }

        if (tid < 2) {
            float acc = bc[tid];
#pragma unroll 8
            for (int k = 0; k < H_; k++) acc += Wc[tid*H_ + k] * hs[k];
            out[tid] = acc;
        }
        if (tid < H_) out[2 + tid] = hs[tid];
    }
}

// ---------- launch ----------
extern "C" void kernel_launch(void* const* d_in, const int* in_sizes, int n_in,
                              void* d_out, int out_size) {
    const float* x    = (const float*)d_in[0];
    const int*   ei   = (const int*)  d_in[1];
    const float* W1   = (const float*)d_in[2];
    const float* b1   = (const float*)d_in[3];
    const float* g1   = (const float*)d_in[4];
    const float* be1  = (const float*)d_in[5];
    const float* m1   = (const float*)d_in[6];
    const float* v1   = (const float*)d_in[7];
    const float* W2   = (const float*)d_in[8];
    const float* b2   = (const float*)d_in[9];
    const float* g2   = (const float*)d_in[10];
    const float* be2  = (const float*)d_in[11];
    const float* m2   = (const float*)d_in[12];
    const float* v2   = (const float*)d_in[13];
    const float* Wih0 = (const float*)d_in[14];
    const float* Whh0 = (const float*)d_in[15];
    const float* bih0 = (const float*)d_in[16];
    const float* bhh0 = (const float*)d_in[17];
    const float* Wih1 = (const float*)d_in[18];
    const float* Whh1 = (const float*)d_in[19];
    const float* bih1 = (const float*)d_in[20];
    const float* bhh1 = (const float*)d_in[21];
    const float* Wc   = (const float*)d_in[22];
    const float* bc   = (const float*)d_in[23];

    void* curp = nullptr;
    cudaGetSymbolAddress(&curp, g_cursor);
    cudaMemsetAsync(curp, 0, SCAN_N * sizeof(int));

    k_fillb <<<(TE/4 + 255)/256, 256>>>(ei, Wih0, Whh0, Wih1, Whh1,
                                        bih0, bhh0, bih1, bhh1);
    k_prep  <<<(SCAN_N*16 + 511)/512, 512>>>(x);
    k_gather<<<dim3(148, T_), 256>>>();
    k_mmtc  <<<dim3(37, T_), 256>>>(W1, b1, g1, be1, m1, v1);
    k_final <<<2, 512>>>(W2, b2, g2, be2, m2, v2, Wc, bc, (float*)d_out);
}